// round 2
// baseline (speedup 1.0000x reference)
#include <cuda_runtime.h>

// ResidualVectorQuantizer fused fp32 kernel.
// B=65536 rows, C=1024, D=256, K=2048 codes, 4 codebooks.
// One CTA = 32 rows, full pipeline fused; residual lives in smem.
// Output layout (float32): [z_q (B*C) | vq_loss | enc_loss | cbk_loss |
//                           codes (B*4) | latents (B*4*D)]

constexpr int Bn  = 65536;
constexpr int Cc  = 1024;
constexpr int Dd  = 256;
constexpr int Kk  = 2048;
constexpr int NCB = 4;
constexpr int BR  = 32;     // rows per CTA
constexpr int NT  = 256;    // threads per CTA
constexpr int CBT = 132;    // padded stride for transposed cb tile

__device__ double g_loss_acc;
__device__ float  g_c2[NCB * Kk];

// Precompute |cb_k|^2 per code, zero loss accumulator.
__global__ void rvq_prep_kernel(const float* __restrict__ cb) {
    int idx = blockIdx.x * blockDim.x + threadIdx.x;   // 0 .. 8191
    if (idx == 0) g_loss_acc = 0.0;
    const float* row = cb + (long)idx * Dd;
    float s = 0.f;
    #pragma unroll 8
    for (int d = 0; d < Dd; d++) s = fmaf(row[d], row[d], s);
    g_c2[idx] = s;
}

__global__ __launch_bounds__(NT, 1) void rvq_main_kernel(
    const float* __restrict__ z,  const float* __restrict__ cb,
    const float* __restrict__ Wi, const float* __restrict__ bi,
    const float* __restrict__ Wo, const float* __restrict__ bo,
    float* __restrict__ out, long out_elems, int fullout)
{
    extern __shared__ __align__(16) float sm[];
    float* resid = sm;                       // [32][1024]
    float* ze    = resid + BR * Cc;          // [32][256]
    float* wt    = ze + BR * Dd;             // 8192 floats (weight / cbT tiles)
    float* srow  = wt + 8192;                // [32]
    float* bval  = srow + 32;                // [32]
    int*   bidx  = (int*)(bval + 32);        // [32]
    float* lred  = (float*)(bidx + 32);      // [8]

    const int tid   = threadIdx.x;
    const int warp  = tid >> 5;
    const int lane  = tid & 31;
    const int rbase = warp * 4;              // this warp's 4 rows
    const int cbase = lane * 8;              // this lane's 8 cols (GEMM1/3)
    const long row0 = (long)blockIdx.x * BR;

    const long SC_OFF   = (long)Bn * Cc;
    const long CODE_OFF = SC_OFF + 3;
    const long LAT_OFF  = CODE_OFF + (long)Bn * NCB;

    // ---- load residual tile (z) ----
    {
        const float4* zg = (const float4*)(z + row0 * Cc);
        float4* rs = (float4*)resid;
        #pragma unroll
        for (int it = 0; it < 32; it++) rs[tid + NT * it] = zg[tid + NT * it];
    }
    __syncthreads();

    float loss_local = 0.f;

    for (int i = 0; i < NCB; i++) {
        const float* Wi_i = Wi + (long)i * Cc * Dd;
        const float* cb_i = cb + (long)i * Kk * Dd;
        const float* Wo_i = Wo + (long)i * Dd * Cc;
        const float* c2_i = g_c2 + i * Kk;

        // ================= Phase A: z_e = resid @ W_in + b_in =============
        float acc[4][8];
        #pragma unroll
        for (int r = 0; r < 4; r++)
            #pragma unroll
            for (int j = 0; j < 8; j++) acc[r][j] = 0.f;

        for (int kt = 0; kt < Cc; kt += 32) {
            __syncthreads();
            {   // stage W_in tile [32][256] (contiguous rows)
                const float4* g = (const float4*)(Wi_i + (long)kt * Dd);
                float4* s4 = (float4*)wt;
                #pragma unroll
                for (int it = 0; it < 8; it++) s4[tid + NT * it] = g[tid + NT * it];
            }
            __syncthreads();
            #pragma unroll 8
            for (int kk = 0; kk < 32; kk++) {
                const int kb = kt + kk;
                float a[4];
                #pragma unroll
                for (int r = 0; r < 4; r++) a[r] = resid[(rbase + r) * Cc + kb];
                const float4 b0 = *reinterpret_cast<const float4*>(&wt[kk * Dd + cbase]);
                const float4 b1 = *reinterpret_cast<const float4*>(&wt[kk * Dd + cbase + 4]);
                #pragma unroll
                for (int r = 0; r < 4; r++) {
                    acc[r][0] = fmaf(a[r], b0.x, acc[r][0]);
                    acc[r][1] = fmaf(a[r], b0.y, acc[r][1]);
                    acc[r][2] = fmaf(a[r], b0.z, acc[r][2]);
                    acc[r][3] = fmaf(a[r], b0.w, acc[r][3]);
                    acc[r][4] = fmaf(a[r], b1.x, acc[r][4]);
                    acc[r][5] = fmaf(a[r], b1.y, acc[r][5]);
                    acc[r][6] = fmaf(a[r], b1.z, acc[r][6]);
                    acc[r][7] = fmaf(a[r], b1.w, acc[r][7]);
                }
            }
        }
        __syncthreads();
        // epilogue: add bias, store z_e, write latents
        #pragma unroll
        for (int r = 0; r < 4; r++) {
            const int grow = rbase + r;
            float v[8];
            #pragma unroll
            for (int j = 0; j < 8; j++) v[j] = acc[r][j] + bi[i * Dd + cbase + j];
            *reinterpret_cast<float4*>(&ze[grow * Dd + cbase])     = make_float4(v[0], v[1], v[2], v[3]);
            *reinterpret_cast<float4*>(&ze[grow * Dd + cbase + 4]) = make_float4(v[4], v[5], v[6], v[7]);
            if (fullout) {
                long o = LAT_OFF + (row0 + grow) * (long)(NCB * Dd) + (long)i * Dd + cbase;
                if (o + 7 < out_elems) {
                    #pragma unroll
                    for (int j = 0; j < 8; j++) out[o + j] = v[j];
                }
            }
        }
        if (tid < BR) { bval[tid] = __int_as_float(0x7f800000); bidx[tid] = 0; }
        __syncthreads();

        // per-row |z_e|^2
        {
            const int r = tid >> 3, seg = tid & 7;
            const float* zr = ze + r * Dd + seg * 32;
            float s = 0.f;
            #pragma unroll
            for (int d = 0; d < 32; d++) s = fmaf(zr[d], zr[d], s);
            s += __shfl_down_sync(0xffffffffu, s, 4, 8);
            s += __shfl_down_sync(0xffffffffu, s, 2, 8);
            s += __shfl_down_sync(0xffffffffu, s, 1, 8);
            if (seg == 0) srow[r] = s;
        }
        __syncthreads();

        // ============ Phase B: distances + argmin over K=2048 =============
        for (int kc = 0; kc < Kk; kc += 128) {
            float dot[4][4];
            #pragma unroll
            for (int r = 0; r < 4; r++)
                #pragma unroll
                for (int c = 0; c < 4; c++) dot[r][c] = 0.f;

            for (int dt = 0; dt < Dd; dt += 32) {
                __syncthreads();
                // stage transposed cb tile: cbT[d (32)][code (128)] stride CBT
                #pragma unroll
                for (int it = 0; it < 4; it++) {
                    int f = tid + NT * it;          // 0..1023
                    int c = f >> 3, j = f & 7;
                    float4 v = *reinterpret_cast<const float4*>(
                        &cb_i[(long)(kc + c) * Dd + dt + 4 * j]);
                    wt[(4 * j + 0) * CBT + c] = v.x;
                    wt[(4 * j + 1) * CBT + c] = v.y;
                    wt[(4 * j + 2) * CBT + c] = v.z;
                    wt[(4 * j + 3) * CBT + c] = v.w;
                }
                __syncthreads();
                #pragma unroll 8
                for (int dd = 0; dd < 32; dd++) {
                    float a[4];
                    #pragma unroll
                    for (int r = 0; r < 4; r++) a[r] = ze[(rbase + r) * Dd + dt + dd];
                    const float4 bb = *reinterpret_cast<const float4*>(&wt[dd * CBT + lane * 4]);
                    #pragma unroll
                    for (int r = 0; r < 4; r++) {
                        dot[r][0] = fmaf(a[r], bb.x, dot[r][0]);
                        dot[r][1] = fmaf(a[r], bb.y, dot[r][1]);
                        dot[r][2] = fmaf(a[r], bb.z, dot[r][2]);
                        dot[r][3] = fmaf(a[r], bb.w, dot[r][3]);
                    }
                }
            }
            // finalize distances (mimic ref rounding: (s - 2*dot) + c2) + argmin
            float c2v[4];
            #pragma unroll
            for (int c = 0; c < 4; c++) c2v[c] = c2_i[kc + lane * 4 + c];
            #pragma unroll
            for (int r = 0; r < 4; r++) {
                const float sr = srow[rbase + r];
                float mval = __int_as_float(0x7f800000);
                int   midx = 0;
                #pragma unroll
                for (int c = 0; c < 4; c++) {
                    float t2 = 2.0f * dot[r][c];
                    float u  = sr - t2;
                    float dv = u + c2v[c];
                    int code = kc + lane * 4 + c;
                    if (dv < mval) { mval = dv; midx = code; }
                }
                #pragma unroll
                for (int off = 16; off; off >>= 1) {
                    float ov = __shfl_down_sync(0xffffffffu, mval, off);
                    int   oi = __shfl_down_sync(0xffffffffu, midx, off);
                    if (ov < mval || (ov == mval && oi < midx)) { mval = ov; midx = oi; }
                }
                if (lane == 0) {
                    if (mval < bval[rbase + r]) { bval[rbase + r] = mval; bidx[rbase + r] = midx; }
                }
            }
        }
        __syncthreads();

        // ====== Phase C: gather emb, commit loss, straight-through q ======
        {
            float lp = 0.f;
            #pragma unroll
            for (int it = 0; it < 32; it++) {
                int e = tid + NT * it;              // 0..8191
                int r = e >> 8, d = e & 255;
                float zev  = ze[e];
                float emb  = __ldg(&cb_i[(long)bidx[r] * Dd + d]);
                float diff = zev - emb;
                lp = fmaf(diff, diff, lp);
                ze[e] = zev + (emb - zev);          // q (ref rounding order)
            }
            loss_local += lp;
        }
        __syncthreads();

        // ============ Phase D: qi = q @ W_out + b_out; resid -= qi ========
        for (int nc = 0; nc < Cc; nc += 256) {
            float ac2[4][8];
            #pragma unroll
            for (int r = 0; r < 4; r++)
                #pragma unroll
                for (int j = 0; j < 8; j++) ac2[r][j] = 0.f;

            for (int kt = 0; kt < Dd; kt += 32) {
                __syncthreads();
                {   // stage W_out tile [32 rows][256 cols] from strided rows
                    #pragma unroll
                    for (int it = 0; it < 8; it++) {
                        int f4 = tid + NT * it;     // 0..2047
                        int rr = f4 >> 6, cc = f4 & 63;
                        ((float4*)&wt[rr * 256])[cc] =
                            ((const float4*)&Wo_i[(long)(kt + rr) * Cc + nc])[cc];
                    }
                }
                __syncthreads();
                #pragma unroll 8
                for (int kk = 0; kk < 32; kk++) {
                    float a[4];
                    #pragma unroll
                    for (int r = 0; r < 4; r++) a[r] = ze[(rbase + r) * Dd + kt + kk];
                    const float4 b0 = *reinterpret_cast<const float4*>(&wt[kk * 256 + cbase]);
                    const float4 b1 = *reinterpret_cast<const float4*>(&wt[kk * 256 + cbase + 4]);
                    #pragma unroll
                    for (int r = 0; r < 4; r++) {
                        ac2[r][0] = fmaf(a[r], b0.x, ac2[r][0]);
                        ac2[r][1] = fmaf(a[r], b0.y, ac2[r][1]);
                        ac2[r][2] = fmaf(a[r], b0.z, ac2[r][2]);
                        ac2[r][3] = fmaf(a[r], b0.w, ac2[r][3]);
                        ac2[r][4] = fmaf(a[r], b1.x, ac2[r][4]);
                        ac2[r][5] = fmaf(a[r], b1.y, ac2[r][5]);
                        ac2[r][6] = fmaf(a[r], b1.z, ac2[r][6]);
                        ac2[r][7] = fmaf(a[r], b1.w, ac2[r][7]);
                    }
                }
            }
            __syncthreads();
            #pragma unroll
            for (int r = 0; r < 4; r++) {
                const int grow = rbase + r;
                #pragma unroll
                for (int j = 0; j < 8; j++) {
                    float qi = ac2[r][j] + bo[i * Cc + nc + cbase + j];
                    resid[grow * Cc + nc + cbase + j] -= qi;
                }
            }
        }
        // codes for this codebook
        if (fullout && tid < BR) {
            long o = CODE_OFF + (row0 + tid) * (long)NCB + i;
            if (o < out_elems) out[o] = (float)bidx[tid];
        }
        __syncthreads();
    }

    // ---- z_q = z - residual_final ----
    {
        const float4* zg = (const float4*)(z + row0 * Cc);
        const float4* rs = (const float4*)resid;
        float4* og = (float4*)(out + row0 * Cc);
        #pragma unroll
        for (int it = 0; it < 32; it++) {
            float4 a = zg[tid + NT * it], b = rs[tid + NT * it];
            og[tid + NT * it] = make_float4(a.x - b.x, a.y - b.y, a.z - b.z, a.w - b.w);
        }
    }

    // ---- commit-loss reduction: one atomic per CTA ----
    #pragma unroll
    for (int off = 16; off; off >>= 1)
        loss_local += __shfl_down_sync(0xffffffffu, loss_local, off);
    if (lane == 0) lred[warp] = loss_local;
    __syncthreads();
    if (warp == 0) {
        float v = (lane < 8) ? lred[lane] : 0.f;
        #pragma unroll
        for (int off = 4; off; off >>= 1)
            v += __shfl_down_sync(0xffffffffu, v, off);
        if (lane == 0) atomicAdd(&g_loss_acc, (double)v);
    }
}

__global__ void rvq_fin_kernel(float* __restrict__ out, long out_elems, int fullout) {
    if (fullout && threadIdx.x == 0) {
        long sc = (long)Bn * Cc;
        if (sc + 2 < out_elems) {
            double t = g_loss_acc;
            float enc = (float)(0.25 * t / ((double)Bn * (double)Dd));
            out[sc + 0] = enc;   // vq_loss = enc + 0.0
            out[sc + 1] = enc;   // enc_loss
            out[sc + 2] = 0.f;   // cbk_loss (CODEBOOK_COST == 0)
        }
    }
}

extern "C" void kernel_launch(void* const* d_in, const int* in_sizes, int n_in,
                              void* d_out, int out_size) {
    const float* z  = (const float*)d_in[0];
    const float* cb = (const float*)d_in[1];
    const float* Wi = (const float*)d_in[2];
    const float* bi = (const float*)d_in[3];
    const float* Wo = (const float*)d_in[4];
    const float* bo = (const float*)d_in[5];
    float* out = (float*)d_out;

    const long out_elems = (long)out_size;
    const int fullout = out_elems > (long)Bn * Cc ? 1 : 0;

    const size_t smem = (size_t)(BR * Cc + BR * Dd + 8192 + 32 + 32 + 32 + 8) * sizeof(float);
    cudaFuncSetAttribute(rvq_main_kernel,
                         cudaFuncAttributeMaxDynamicSharedMemorySize, (int)smem);

    rvq_prep_kernel<<<(NCB * Kk) / 256, 256>>>(cb);
    rvq_main_kernel<<<Bn / BR, NT, smem>>>(z, cb, Wi, bi, Wo, bo, out, out_elems, fullout);
    rvq_fin_kernel<<<1, 32>>>(out, out_elems, fullout);
}

// round 4
// speedup vs baseline: 1.4357x; 1.4357x over previous
#include <cuda_runtime.h>
#include <cstdint>

// ResidualVectorQuantizer fused fp32 kernel, f32x2 (FFMA2) edition.
// B=65536, C=1024, D=256, K=2048, 4 codebooks. CTA = 32 rows, occ 1.
// Warp w: row-group (w&3)*8, col-group (w>>2)*128; thread tile 8 rows x 4 cols.
// NOTE: latents region starts at offset == 3 (mod 4) floats -> scalar stores only.

constexpr int Bn  = 65536;
constexpr int Cc  = 1024;
constexpr int Dd  = 256;
constexpr int Kk  = 2048;
constexpr int NCB = 4;
constexpr int BR  = 32;
constexpr int NT  = 256;
constexpr int CBT = 132;                 // padded code-stride for cbT tiles

__device__ double g_loss_acc;
__device__ __align__(16) float g_c2[NCB * Kk];

// ---------------- f32x2 helpers ----------------
__device__ __forceinline__ unsigned long long pk2(float lo, float hi) {
    unsigned long long r;
    asm("mov.b64 %0, {%1, %2};" : "=l"(r) : "f"(lo), "f"(hi));
    return r;
}
__device__ __forceinline__ void upk2(unsigned long long v, float& lo, float& hi) {
    asm("mov.b64 {%0, %1}, %2;" : "=f"(lo), "=f"(hi) : "l"(v));
}
__device__ __forceinline__ void ffma2(unsigned long long& acc,
                                      unsigned long long a, unsigned long long b) {
    asm("fma.rn.f32x2 %0, %1, %2, %3;" : "=l"(acc) : "l"(a), "l"(b), "l"(acc));
}
__device__ __forceinline__ float f4get(const float4& v, int k) {
    return k == 0 ? v.x : k == 1 ? v.y : k == 2 ? v.z : v.w;
}
// ---------------- cp.async helpers ----------------
__device__ __forceinline__ void cp16(uint32_t dst, const void* src) {
    asm volatile("cp.async.cg.shared.global [%0], [%1], 16;" :: "r"(dst), "l"(src));
}
__device__ __forceinline__ void cp_commit() { asm volatile("cp.async.commit_group;"); }
__device__ __forceinline__ void cp_wait0()  { asm volatile("cp.async.wait_group 0;"); }
__device__ __forceinline__ void cp_wait1()  { asm volatile("cp.async.wait_group 1;"); }

// Precompute |cb_k|^2, zero loss accumulator.
__global__ void rvq_prep_kernel(const float* __restrict__ cb) {
    int idx = blockIdx.x * blockDim.x + threadIdx.x;
    if (idx == 0) g_loss_acc = 0.0;
    const float* row = cb + (long)idx * Dd;
    float s = 0.f;
    #pragma unroll 8
    for (int d = 0; d < Dd; d++) s = fmaf(row[d], row[d], s);
    g_c2[idx] = s;
}

__global__ __launch_bounds__(NT, 1) void rvq_main_kernel(
    const float* __restrict__ z,  const float* __restrict__ cb,
    const float* __restrict__ Wi, const float* __restrict__ bi,
    const float* __restrict__ Wo, const float* __restrict__ bo,
    float* __restrict__ out, long out_elems, int fullout)
{
    extern __shared__ __align__(16) float sm[];
    float* resid = sm;                               // [32][1024]
    float* ze    = resid + BR * Cc;                  // [32][256]
    float* wt    = ze + BR * Dd;                     // 16384 floats (2 x 8192)
    unsigned long long* sbest = (unsigned long long*)(wt + 16384);  // [32]
    float* srow  = (float*)(sbest + 32);             // [32]
    float* lred  = srow + 32;                        // [8]

    const int tid  = threadIdx.x;
    const int warp = tid >> 5;
    const int lane = tid & 31;
    const int rA   = (warp & 3) * 8;                 // 8 rows
    const int colg = warp >> 2;                      // 0/1
    const int col0 = colg * 128 + lane * 4;          // 4 cols (phases A/D)
    const long row0 = (long)blockIdx.x * BR;

    const uint32_t wt_s = (uint32_t)__cvta_generic_to_shared(wt);

    const long SC_OFF   = (long)Bn * Cc;
    const long CODE_OFF = SC_OFF + 3;
    const long LAT_OFF  = CODE_OFF + (long)Bn * NCB;   // == 3 (mod 4): scalar stores!

    // ---- load residual tile ----
    {
        const float4* zg = (const float4*)(z + row0 * Cc);
        float4* rs = (float4*)resid;
        #pragma unroll
        for (int it = 0; it < 32; it++) rs[tid + NT * it] = zg[tid + NT * it];
    }
    __syncthreads();

    float loss_local = 0.f;

    for (int i = 0; i < NCB; i++) {
        const float* Wi_i = Wi + (long)i * Cc * Dd;
        const float* cb_i = cb + (long)i * Kk * Dd;
        const float* Wo_i = Wo + (long)i * Dd * Cc;
        const float* c2_i = g_c2 + i * Kk;

        // ============ Phase A: z_e = resid @ W_in + b_in (f32x2) ==========
        {
            unsigned long long acc[16];
            #pragma unroll
            for (int j = 0; j < 16; j++) acc[j] = 0ull;

            // prologue stage tile 0
            #pragma unroll
            for (int s = 0; s < 8; s++) {
                int f = tid + NT * s;
                cp16(wt_s + (uint32_t)f * 16, Wi_i + (long)f * 4);
            }
            cp_commit();

            for (int t = 0; t < 32; t++) {
                if (t < 31) {
                    const float* src = Wi_i + (long)(t + 1) * 8192;
                    uint32_t db = wt_s + ((t + 1) & 1) * 32768;
                    #pragma unroll
                    for (int s = 0; s < 8; s++) {
                        int f = tid + NT * s;
                        cp16(db + (uint32_t)f * 16, src + (long)f * 4);
                    }
                    cp_commit();
                    cp_wait1();
                } else cp_wait0();
                __syncthreads();
                const float* w = wt + (t & 1) * 8192;
                #pragma unroll 2
                for (int kg = 0; kg < 8; kg++) {
                    float4 a4[8];
                    #pragma unroll
                    for (int r = 0; r < 8; r++)
                        a4[r] = *(const float4*)&resid[(rA + r) * Cc + t * 32 + kg * 4];
                    #pragma unroll
                    for (int kk = 0; kk < 4; kk++) {
                        float4 b = *(const float4*)&w[(kg * 4 + kk) * 256 + col0];
                        unsigned long long b01 = pk2(b.x, b.y), b23 = pk2(b.z, b.w);
                        #pragma unroll
                        for (int r = 0; r < 8; r++) {
                            float av = f4get(a4[r], kk);
                            unsigned long long aa = pk2(av, av);
                            ffma2(acc[2 * r],     aa, b01);
                            ffma2(acc[2 * r + 1], aa, b23);
                        }
                    }
                }
                __syncthreads();
            }
            // epilogue: bias, ze store, latents (SCALAR stores: region is mod-4 == 3)
            float4 bia = *(const float4*)&bi[i * Dd + col0];
            #pragma unroll
            for (int r = 0; r < 8; r++) {
                float v0, v1, v2, v3;
                upk2(acc[2 * r], v0, v1);
                upk2(acc[2 * r + 1], v2, v3);
                v0 += bia.x; v1 += bia.y; v2 += bia.z; v3 += bia.w;
                *(float4*)&ze[(rA + r) * Dd + col0] = make_float4(v0, v1, v2, v3);
                if (fullout) {
                    long o = LAT_OFF + (row0 + rA + r) * (long)(NCB * Dd) + (long)i * Dd + col0;
                    if (o + 3 < out_elems) {
                        out[o + 0] = v0; out[o + 1] = v1;
                        out[o + 2] = v2; out[o + 3] = v3;
                    }
                }
            }
        }
        if (tid < BR) sbest[tid] = ~0ull;
        __syncthreads();

        // per-row |z_e|^2
        {
            const int r = tid >> 3, seg = tid & 7;
            const float* zr = ze + r * Dd + seg * 32;
            float s = 0.f;
            #pragma unroll
            for (int d = 0; d < 32; d++) s = fmaf(zr[d], zr[d], s);
            s += __shfl_down_sync(0xffffffffu, s, 4, 8);
            s += __shfl_down_sync(0xffffffffu, s, 2, 8);
            s += __shfl_down_sync(0xffffffffu, s, 1, 8);
            if (seg == 0) srow[r] = s;
        }
        __syncthreads();

        // ====== Phase B: distances + argmin, 2 x 128-code tiles / iter ====
        for (int kc = 0; kc < Kk; kc += 256) {
            unsigned long long dot[16];
            #pragma unroll
            for (int j = 0; j < 16; j++) dot[j] = 0ull;

            float4 stg[8];
            #pragma unroll
            for (int s = 0; s < 8; s++) {
                int f = tid + NT * s, half = f >> 10, g = f & 1023;
                int c = g >> 3, jj = g & 7;
                stg[s] = *(const float4*)&cb_i[(long)(kc + half * 128 + c) * Dd + 4 * jj];
            }
            for (int dt = 0; dt < 8; dt++) {
                __syncthreads();
                #pragma unroll
                for (int s = 0; s < 8; s++) {
                    int f = tid + NT * s, half = f >> 10, g = f & 1023;
                    int c = g >> 3, jj = g & 7;
                    float* d0 = &wt[half * 4224 + (4 * jj) * CBT + c];
                    d0[0 * CBT] = stg[s].x; d0[1 * CBT] = stg[s].y;
                    d0[2 * CBT] = stg[s].z; d0[3 * CBT] = stg[s].w;
                }
                __syncthreads();
                if (dt < 7) {
                    #pragma unroll
                    for (int s = 0; s < 8; s++) {
                        int f = tid + NT * s, half = f >> 10, g = f & 1023;
                        int c = g >> 3, jj = g & 7;
                        stg[s] = *(const float4*)&cb_i[(long)(kc + half * 128 + c) * Dd
                                                       + (dt + 1) * 32 + 4 * jj];
                    }
                }
                const float* wb = wt + colg * 4224;
                #pragma unroll 2
                for (int dg = 0; dg < 8; dg++) {
                    float4 a4[8];
                    #pragma unroll
                    for (int r = 0; r < 8; r++)
                        a4[r] = *(const float4*)&ze[(rA + r) * Dd + dt * 32 + dg * 4];
                    #pragma unroll
                    for (int dd = 0; dd < 4; dd++) {
                        float4 b = *(const float4*)&wb[(dg * 4 + dd) * CBT + lane * 4];
                        unsigned long long b01 = pk2(b.x, b.y), b23 = pk2(b.z, b.w);
                        #pragma unroll
                        for (int r = 0; r < 8; r++) {
                            float av = f4get(a4[r], dd);
                            unsigned long long aa = pk2(av, av);
                            ffma2(dot[2 * r],     aa, b01);
                            ffma2(dot[2 * r + 1], aa, b23);
                        }
                    }
                }
            }
            // argmin epilogue (ref rounding: (s - 2*dot) + c2)
            const int code0 = kc + colg * 128 + lane * 4;
            float4 c2v = *(const float4*)&c2_i[code0];
            #pragma unroll
            for (int r = 0; r < 8; r++) {
                const float sr = srow[rA + r];
                float d0, d1, d2, d3;
                upk2(dot[2 * r], d0, d1);
                upk2(dot[2 * r + 1], d2, d3);
                float dv0 = (sr - 2.0f * d0) + c2v.x;
                float dv1 = (sr - 2.0f * d1) + c2v.y;
                float dv2 = (sr - 2.0f * d2) + c2v.z;
                float dv3 = (sr - 2.0f * d3) + c2v.w;
                float mval = dv0; int midx = code0;
                if (dv1 < mval) { mval = dv1; midx = code0 + 1; }
                if (dv2 < mval) { mval = dv2; midx = code0 + 2; }
                if (dv3 < mval) { mval = dv3; midx = code0 + 3; }
                #pragma unroll
                for (int off = 16; off; off >>= 1) {
                    float ov = __shfl_down_sync(0xffffffffu, mval, off);
                    int   oi = __shfl_down_sync(0xffffffffu, midx, off);
                    if (ov < mval || (ov == mval && oi < midx)) { mval = ov; midx = oi; }
                }
                if (lane == 0) {
                    unsigned long long key =
                        ((unsigned long long)__float_as_uint(mval) << 32) | (unsigned)midx;
                    atomicMin(&sbest[rA + r], key);
                }
            }
        }
        __syncthreads();

        // ====== Phase C: gather emb, commit loss, straight-through ========
        {
            float lp = 0.f;
            #pragma unroll
            for (int it = 0; it < 32; it++) {
                int e = tid + NT * it;
                int r = e >> 8, d = e & 255;
                int code = (int)(sbest[r] & 0xffffffffu);
                float zev  = ze[e];
                float emb  = __ldg(&cb_i[(long)code * Dd + d]);
                float diff = zev - emb;
                lp = fmaf(diff, diff, lp);
                ze[e] = zev + (emb - zev);
            }
            loss_local += lp;
        }
        if (fullout && tid < BR) {
            long o = CODE_OFF + (row0 + tid) * (long)NCB + i;
            if (o < out_elems) out[o] = (float)(int)(sbest[tid] & 0xffffffffu);
        }
        __syncthreads();

        // ============ Phase D: resid -= q @ W_out + b_out (f32x2) =========
        for (int nc = 0; nc < Cc; nc += 256) {
            unsigned long long acc[16];
            #pragma unroll
            for (int j = 0; j < 16; j++) acc[j] = 0ull;

            #pragma unroll
            for (int s = 0; s < 8; s++) {
                int f = tid + NT * s, rr = f >> 6, cc = f & 63;
                cp16(wt_s + (uint32_t)f * 16, Wo_i + (long)rr * Cc + nc + cc * 4);
            }
            cp_commit();

            for (int t = 0; t < 8; t++) {
                if (t < 7) {
                    uint32_t db = wt_s + ((t + 1) & 1) * 32768;
                    #pragma unroll
                    for (int s = 0; s < 8; s++) {
                        int f = tid + NT * s, rr = f >> 6, cc = f & 63;
                        cp16(db + (uint32_t)f * 16,
                             Wo_i + (long)((t + 1) * 32 + rr) * Cc + nc + cc * 4);
                    }
                    cp_commit();
                    cp_wait1();
                } else cp_wait0();
                __syncthreads();
                const float* w = wt + (t & 1) * 8192;
                #pragma unroll 2
                for (int kg = 0; kg < 8; kg++) {
                    float4 a4[8];
                    #pragma unroll
                    for (int r = 0; r < 8; r++)
                        a4[r] = *(const float4*)&ze[(rA + r) * Dd + t * 32 + kg * 4];
                    #pragma unroll
                    for (int kk = 0; kk < 4; kk++) {
                        float4 b = *(const float4*)&w[(kg * 4 + kk) * 256 + col0];
                        unsigned long long b01 = pk2(b.x, b.y), b23 = pk2(b.z, b.w);
                        #pragma unroll
                        for (int r = 0; r < 8; r++) {
                            float av = f4get(a4[r], kk);
                            unsigned long long aa = pk2(av, av);
                            ffma2(acc[2 * r],     aa, b01);
                            ffma2(acc[2 * r + 1], aa, b23);
                        }
                    }
                }
                __syncthreads();
            }
            float4 bo4 = *(const float4*)&bo[i * Cc + nc + col0];
            #pragma unroll
            for (int r = 0; r < 8; r++) {
                float v0, v1, v2, v3;
                upk2(acc[2 * r], v0, v1);
                upk2(acc[2 * r + 1], v2, v3);
                float4* rp = (float4*)&resid[(rA + r) * Cc + nc + col0];
                float4 rv = *rp;
                rv.x -= v0 + bo4.x; rv.y -= v1 + bo4.y;
                rv.z -= v2 + bo4.z; rv.w -= v3 + bo4.w;
                *rp = rv;
            }
        }
        __syncthreads();
    }

    // ---- z_q = z - residual_final ----
    {
        const float4* zg = (const float4*)(z + row0 * Cc);
        const float4* rs = (const float4*)resid;
        float4* og = (float4*)(out + row0 * Cc);
        #pragma unroll
        for (int it = 0; it < 32; it++) {
            float4 a = zg[tid + NT * it], b = rs[tid + NT * it];
            og[tid + NT * it] = make_float4(a.x - b.x, a.y - b.y, a.z - b.z, a.w - b.w);
        }
    }

    // ---- loss reduction ----
    #pragma unroll
    for (int off = 16; off; off >>= 1)
        loss_local += __shfl_down_sync(0xffffffffu, loss_local, off);
    if (lane == 0) lred[warp] = loss_local;
    __syncthreads();
    if (warp == 0) {
        float v = (lane < 8) ? lred[lane] : 0.f;
        #pragma unroll
        for (int off = 4; off; off >>= 1)
            v += __shfl_down_sync(0xffffffffu, v, off);
        if (lane == 0) atomicAdd(&g_loss_acc, (double)v);
    }
}

__global__ void rvq_fin_kernel(float* __restrict__ out, long out_elems, int fullout) {
    if (fullout && threadIdx.x == 0) {
        long sc = (long)Bn * Cc;
        if (sc + 2 < out_elems) {
            double t = g_loss_acc;
            float enc = (float)(0.25 * t / ((double)Bn * (double)Dd));
            out[sc + 0] = enc;
            out[sc + 1] = enc;
            out[sc + 2] = 0.f;
        }
    }
}

extern "C" void kernel_launch(void* const* d_in, const int* in_sizes, int n_in,
                              void* d_out, int out_size) {
    const float* z  = (const float*)d_in[0];
    const float* cb = (const float*)d_in[1];
    const float* Wi = (const float*)d_in[2];
    const float* bi = (const float*)d_in[3];
    const float* Wo = (const float*)d_in[4];
    const float* bo = (const float*)d_in[5];
    float* out = (float*)d_out;

    const long out_elems = (long)out_size;
    const int fullout = out_elems > (long)Bn * Cc ? 1 : 0;

    const size_t smem = (size_t)(BR * Cc + BR * Dd + 16384) * sizeof(float)
                      + 32 * sizeof(unsigned long long) + (32 + 8) * sizeof(float);
    cudaFuncSetAttribute(rvq_main_kernel,
                         cudaFuncAttributeMaxDynamicSharedMemorySize, (int)smem);

    rvq_prep_kernel<<<(NCB * Kk) / 256, 256>>>(cb);
    rvq_main_kernel<<<Bn / BR, NT, smem>>>(z, cb, Wi, bi, Wo, bo, out, out_elems, fullout);
    rvq_fin_kernel<<<1, 32>>>(out, out_elems, fullout);
}